// round 1
// baseline (speedup 1.0000x reference)
#include <cuda_runtime.h>

// Problem constants
#define BB 32
#define SS 1024
#define EE 768
#define HH 64
#define LL 2

// Scratch (static device allocation is the sanctioned mechanism)
__device__ float g_q[(size_t)BB * SS * EE];
__device__ float g_k[(size_t)BB * SS * EE];
__device__ float g_v[(size_t)BB * SS * EE];
__device__ float g_s[(size_t)BB * SS * SS];
__device__ float g_a[(size_t)BB * SS * EE];
__device__ float g_w1t[EE * HH];

// ---------------------------------------------------------------------------
// Tiled SGEMM: C[m,n] = sum_k A[m,k] * B(k,n) + bias[n]
//   B_KMAJOR = true : B stored [N,K] row-major (C = A @ B^T)
//   B_KMAJOR = false: B stored [K,N] row-major (C = A @ B)
//   CAUSAL: skip tiles strictly above the diagonal (scores GEMM)
//   PVLIM : limit K range to m0+128 (P·V GEMM, probs are exactly 0 beyond)
// All dims assumed multiples of tile sizes (true for this problem).
// ---------------------------------------------------------------------------
template<bool B_KMAJOR, bool CAUSAL, bool PVLIM>
__global__ __launch_bounds__(256) void gemm128(
    const float* __restrict__ A, const float* __restrict__ B,
    const float* __restrict__ bias, float* __restrict__ C,
    int M, int N, int K, int lda, int ldb, int ldc,
    long long sA, long long sB, long long sC)
{
    if (CAUSAL && blockIdx.x > blockIdx.y) return;

    A += (long long)blockIdx.z * sA;
    B += (long long)blockIdx.z * sB;
    C += (long long)blockIdx.z * sC;

    const int m0 = blockIdx.y * 128;
    const int n0 = blockIdx.x * 128;
    int kend = K;
    if (PVLIM) kend = min(K, m0 + 128);

    __shared__ float As[16][132];   // +4 pad keeps float4 alignment, trims conflicts
    __shared__ float Bs[16][132];

    const int tid = threadIdx.x;
    const int tx = tid & 15;
    const int ty = tid >> 4;

    float acc[8][8];
#pragma unroll
    for (int i = 0; i < 8; i++)
#pragma unroll
        for (int j = 0; j < 8; j++) acc[i][j] = 0.f;

    for (int k0 = 0; k0 < kend; k0 += 16) {
        // A tile: 128 rows x 16 k, stored transposed As[k][m]
#pragma unroll
        for (int t = 0; t < 2; t++) {
            int v = tid + t * 256;
            int row = v >> 2;
            int kc  = (v & 3) << 2;
            const float4 a = *reinterpret_cast<const float4*>(
                &A[(long long)(m0 + row) * lda + k0 + kc]);
            As[kc + 0][row] = a.x; As[kc + 1][row] = a.y;
            As[kc + 2][row] = a.z; As[kc + 3][row] = a.w;
        }
        if (B_KMAJOR) {
#pragma unroll
            for (int t = 0; t < 2; t++) {
                int v = tid + t * 256;
                int row = v >> 2;          // n index
                int kc  = (v & 3) << 2;
                const float4 b = *reinterpret_cast<const float4*>(
                    &B[(long long)(n0 + row) * ldb + k0 + kc]);
                Bs[kc + 0][row] = b.x; Bs[kc + 1][row] = b.y;
                Bs[kc + 2][row] = b.z; Bs[kc + 3][row] = b.w;
            }
        } else {
#pragma unroll
            for (int t = 0; t < 2; t++) {
                int v = tid + t * 256;
                int kr = v >> 5;
                int nc = (v & 31) << 2;
                *reinterpret_cast<float4*>(&Bs[kr][nc]) =
                    *reinterpret_cast<const float4*>(
                        &B[(long long)(k0 + kr) * ldb + n0 + nc]);
            }
        }
        __syncthreads();

#pragma unroll
        for (int kk = 0; kk < 16; kk++) {
            float ar[8], br[8];
            *reinterpret_cast<float4*>(ar)     = *reinterpret_cast<const float4*>(&As[kk][ty * 8]);
            *reinterpret_cast<float4*>(ar + 4) = *reinterpret_cast<const float4*>(&As[kk][ty * 8 + 4]);
            *reinterpret_cast<float4*>(br)     = *reinterpret_cast<const float4*>(&Bs[kk][tx * 8]);
            *reinterpret_cast<float4*>(br + 4) = *reinterpret_cast<const float4*>(&Bs[kk][tx * 8 + 4]);
#pragma unroll
            for (int i = 0; i < 8; i++)
#pragma unroll
                for (int j = 0; j < 8; j++)
                    acc[i][j] += ar[i] * br[j];
        }
        __syncthreads();
    }

#pragma unroll
    for (int i = 0; i < 8; i++) {
        int m = m0 + ty * 8 + i;
#pragma unroll
        for (int j4 = 0; j4 < 2; j4++) {
            int n = n0 + tx * 8 + j4 * 4;
            float4 r;
            r.x = acc[i][j4 * 4 + 0]; r.y = acc[i][j4 * 4 + 1];
            r.z = acc[i][j4 * 4 + 2]; r.w = acc[i][j4 * 4 + 3];
            if (bias) {
                r.x += bias[n + 0]; r.y += bias[n + 1];
                r.z += bias[n + 2]; r.w += bias[n + 3];
            }
            *reinterpret_cast<float4*>(&C[(long long)m * ldc + n]) = r;
        }
    }
}

// ---------------------------------------------------------------------------
// Row-wise causal softmax with attention-mask additive bias.
// One block per (i, b) row of 1024. Writes the full row (masked entries
// become exactly 0.0f: exp underflow, matching fp32 reference).
// ---------------------------------------------------------------------------
__global__ __launch_bounds__(256) void softmax_causal(
    float* __restrict__ Smat, const float* __restrict__ amask)
{
    const int i = blockIdx.x;
    const int b = blockIdx.y;
    float* row = Smat + ((long long)b * SS + i) * SS;
    const float* am = amask + (long long)b * SS;
    const int tid = threadIdx.x;

    float vals[4];
    float mx = -1e30f;
#pragma unroll
    for (int r = 0; r < 4; r++) {
        int j = r * 256 + tid;
        float s = (j <= i) ? row[j] : -10000.0f;
        s += (1.0f - am[j]) * -10000.0f;
        vals[r] = s;
        mx = fmaxf(mx, s);
    }

    __shared__ float red[8];
#pragma unroll
    for (int o = 16; o > 0; o >>= 1) mx = fmaxf(mx, __shfl_xor_sync(0xffffffffu, mx, o));
    if ((tid & 31) == 0) red[tid >> 5] = mx;
    __syncthreads();
    mx = red[0];
#pragma unroll
    for (int w = 1; w < 8; w++) mx = fmaxf(mx, red[w]);

    float sum = 0.f;
#pragma unroll
    for (int r = 0; r < 4; r++) {
        vals[r] = __expf(vals[r] - mx);
        sum += vals[r];
    }
#pragma unroll
    for (int o = 16; o > 0; o >>= 1) sum += __shfl_xor_sync(0xffffffffu, sum, o);
    __syncthreads();
    if ((tid & 31) == 0) red[tid >> 5] = sum;
    __syncthreads();
    sum = 0.f;
#pragma unroll
    for (int w = 0; w < 8; w++) sum += red[w];

    const float inv = 1.0f / sum;
#pragma unroll
    for (int r = 0; r < 4; r++) row[r * 256 + tid] = vals[r] * inv;
}

// ---------------------------------------------------------------------------
// W1 [64,768] -> W1t [768,64] so the MLP reads it coalesced.
// ---------------------------------------------------------------------------
__global__ void transpose_w1(const float* __restrict__ W1, float* __restrict__ W1t)
{
    int idx = blockIdx.x * 256 + threadIdx.x;
    if (idx < HH * EE) {
        int c = idx / EE;
        int e = idx % EE;
        W1t[e * HH + c] = W1[idx];
    }
}

// ---------------------------------------------------------------------------
// Fused MLP head: out = relu(X @ W1^T + b1) @ W2^T + b2
// 4 rows per block; thread (c = t&63, rr = t>>6) computes h[rr][c].
// ---------------------------------------------------------------------------
__global__ __launch_bounds__(256) void mlp_kernel(
    const float* __restrict__ X, const float* __restrict__ W1t,
    const float* __restrict__ b1, const float* __restrict__ W2,
    const float* __restrict__ b2, float* __restrict__ out)
{
    __shared__ float xs[4][EE];
    __shared__ float hs[4][HH];
    const int row0 = blockIdx.x * 4;
    const int tid = threadIdx.x;

    for (int v = tid; v < 4 * EE; v += 256)
        xs[v / EE][v % EE] = X[(long long)(row0 + v / EE) * EE + (v % EE)];
    __syncthreads();

    const int c  = tid & 63;
    const int rr = tid >> 6;
    float a0 = 0.f, a1 = 0.f, a2 = 0.f, a3 = 0.f;
#pragma unroll 4
    for (int e = 0; e < EE; e += 4) {
        a0 += xs[rr][e + 0] * W1t[(e + 0) * HH + c];
        a1 += xs[rr][e + 1] * W1t[(e + 1) * HH + c];
        a2 += xs[rr][e + 2] * W1t[(e + 2) * HH + c];
        a3 += xs[rr][e + 3] * W1t[(e + 3) * HH + c];
    }
    float acc = b1[c] + ((a0 + a1) + (a2 + a3));
    hs[rr][c] = fmaxf(acc, 0.f);
    __syncthreads();

    if (tid < 4 * LL) {
        int r2 = tid >> 1;
        int l  = tid & 1;
        float s = b2[l];
#pragma unroll
        for (int h = 0; h < HH; h++) s += hs[r2][h] * W2[l * HH + h];
        out[(long long)(row0 + r2) * LL + l] = s;
    }
}

// ---------------------------------------------------------------------------
extern "C" void kernel_launch(void* const* d_in, const int* in_sizes, int n_in,
                              void* d_out, int out_size)
{
    const float* hidden = (const float*)d_in[0];
    const float* amask  = (const float*)d_in[1];
    const float* Wk = (const float*)d_in[2];
    const float* bk = (const float*)d_in[3];
    const float* Wq = (const float*)d_in[4];
    const float* bq = (const float*)d_in[5];
    const float* Wv = (const float*)d_in[6];
    const float* bv = (const float*)d_in[7];
    const float* W1 = (const float*)d_in[8];
    const float* b1 = (const float*)d_in[9];
    const float* W2 = (const float*)d_in[10];
    const float* b2 = (const float*)d_in[11];
    float* out = (float*)d_out;

    float *q, *k, *v, *s, *a, *w1t;
    cudaGetSymbolAddress((void**)&q,   g_q);
    cudaGetSymbolAddress((void**)&k,   g_k);
    cudaGetSymbolAddress((void**)&v,   g_v);
    cudaGetSymbolAddress((void**)&s,   g_s);
    cudaGetSymbolAddress((void**)&a,   g_a);
    cudaGetSymbolAddress((void**)&w1t, g_w1t);

    const dim3 blk(256);
    const int M = BB * SS;

    // QKV projections: C[M, E] = hidden @ W^T + b
    gemm128<true, false, false><<<dim3(EE / 128, M / 128, 1), blk>>>(
        hidden, Wq, bq, q, M, EE, EE, EE, EE, EE, 0, 0, 0);
    gemm128<true, false, false><<<dim3(EE / 128, M / 128, 1), blk>>>(
        hidden, Wk, bk, k, M, EE, EE, EE, EE, EE, 0, 0, 0);
    gemm128<true, false, false><<<dim3(EE / 128, M / 128, 1), blk>>>(
        hidden, Wv, bv, v, M, EE, EE, EE, EE, EE, 0, 0, 0);

    // W1 transpose (independent; overlaps nothing but is tiny)
    transpose_w1<<<(EE * HH + 255) / 256, blk>>>(W1, w1t);

    // Scores: s[b,i,j] = q[b,i,:] . k[b,j,:], causal tile skip
    gemm128<true, true, false><<<dim3(SS / 128, SS / 128, BB), blk>>>(
        q, k, nullptr, s, SS, SS, EE, EE, EE, SS,
        (long long)SS * EE, (long long)SS * EE, (long long)SS * SS);

    // Softmax (causal + attention-mask bias), in place
    softmax_causal<<<dim3(SS, BB), blk>>>(s, amask);

    // a[b,i,:] = p[b,i,:] @ v[b,:,:], K limited by causality
    gemm128<false, false, true><<<dim3(EE / 128, SS / 128, BB), blk>>>(
        s, v, nullptr, a, SS, EE, SS, SS, EE, EE,
        (long long)SS * SS, (long long)SS * EE, (long long)SS * EE);

    // Fused MLP head -> out [B*S, 2]
    mlp_kernel<<<M / 4, blk>>>(a, w1t, b1, W2, b2, out);
}